// round 10
// baseline (speedup 1.0000x reference)
#include <cuda_runtime.h>

#define TILE_W   32          // output cols per block
#define TILE_H   42          // output rows per block
#define IN_R     52          // input rows = TILE_H + 10
#define A_STRIDE 44          // floats per row in A/B planes (11 float4; bank stride 12 -> conflict-free)
#define H_PAD    33          // float4 per row in H (odd -> conflict-free)
#define IMG      512
#define OUTD     502
#define NPLANE   48

// dynamic smem layout (bytes)
#define H_BYTES    (IN_R * H_PAD * 16)               // 27456
#define AP_BYTES   (IN_R * A_STRIDE * 4)             // 9152
#define SMEM_TOTAL (H_BYTES + 2 * AP_BYTES + 64)     // 45824 -> 5 CTAs/SM

__global__ void ssim_zero_kernel(float* out, int n) {
    int i = threadIdx.x;
    if (i < n) out[i] = 0.0f;
}

// pixel extract from lazily-loaded float4 block arrays (constant indices after unroll)
#define PXA(i) ((((i)&3)==0) ? fa[(i)>>2].x : (((i)&3)==1) ? fa[(i)>>2].y : (((i)&3)==2) ? fa[(i)>>2].z : fa[(i)>>2].w)
#define PXB(i) ((((i)&3)==0) ? fb[(i)>>2].x : (((i)&3)==1) ? fb[(i)>>2].y : (((i)&3)==2) ? fb[(i)>>2].z : fb[(i)>>2].w)

__global__ __launch_bounds__(256, 5) void ssim_kernel(const float* __restrict__ img1,
                                                      const float* __restrict__ img2,
                                                      float* __restrict__ out) {
    extern __shared__ char smem_raw[];
    float4 (*H)[H_PAD] = (float4 (*)[H_PAD])(smem_raw);
    float* Ap = (float*)(smem_raw + H_BYTES);
    float* Bp = (float*)(smem_raw + H_BYTES + AP_BYTES);
    float* wsum = (float*)(smem_raw + H_BYTES + 2 * AP_BYTES);

    const int plane = blockIdx.z;
    const int batch = plane / 3;
    const int ox0 = blockIdx.x * TILE_W;
    const int oy0 = blockIdx.y * TILE_H;

    const float4* __restrict__ g1 = (const float4*)(img1 + (size_t)plane * IMG * IMG);
    const float4* __restrict__ g2 = (const float4*)(img2 + (size_t)plane * IMG * IMG);
    const int row4 = IMG / 4;          // 128 float4 per image row
    const int cb0  = ox0 >> 2;         // float4 col of tile origin

    const int tid = threadIdx.x;

    // ---- Phase 0: load 52 rows x 11 float4 per image into A/B planes (saturated).
    //      OOB float4s are fully in or fully out (gx multiple of 4, IMG=512). ----
    #pragma unroll
    for (int i = tid; i < IN_R * 11 * 2; i += 256) {
        const int which = (i >= IN_R * 11);
        const int s  = which ? i - IN_R * 11 : i;
        const int r  = s / 11;
        const int c4 = s - r * 11;
        const int gy  = oy0 + r;
        const int gx4 = cb0 + c4;
        float4 v = make_float4(0.f, 0.f, 0.f, 0.f);
        if (gy < IMG && gx4 < row4) {
            v = __ldg((which ? g2 : g1) + gy * row4 + gx4);
            v.x = __saturatef(v.x); v.y = __saturatef(v.y);
            v.z = __saturatef(v.z); v.w = __saturatef(v.w);
        }
        float* dst = which ? Bp : Ap;
        *(float4*)(dst + r * A_STRIDE + 4 * c4) = v;
    }
    __syncthreads();

    // ---- Phase 1: horizontal sliding 11-sums, span 16. 104 threads:
    //      row = tid % 52, half = tid / 52, c0 = half*16.
    //      Pixels c0..c0+25 come from 7 float4 blocks per image, loaded lazily. ----
    if (tid < 2 * IN_R) {
        const int row = tid % IN_R;
        const int c0  = (tid / IN_R) * 16;
        const float4* Ar = (const float4*)(Ap + row * A_STRIDE) + (c0 >> 2);
        const float4* Br = (const float4*)(Bp + row * A_STRIDE) + (c0 >> 2);
        float4* Hrow = &H[row][c0];

        float4 fa[7], fb[7];
        fa[0] = Ar[0]; fb[0] = Br[0];
        fa[1] = Ar[1]; fb[1] = Br[1];
        fa[2] = Ar[2]; fb[2] = Br[2];

        float sa = 0.f, sb = 0.f, sp = 0.f, sm = 0.f;
        #pragma unroll
        for (int k = 0; k < 10; k++) {
            const float a = PXA(k), b = PXB(k);
            const float p = a + b, m = a - b;
            sa += a; sb += b; sp += p * p; sm += m * m;
        }
        #pragma unroll
        for (int j = 0; j < 16; j++) {
            if (j == 2)  { fa[3] = Ar[3]; fb[3] = Br[3]; }
            if (j == 6)  { fa[4] = Ar[4]; fb[4] = Br[4]; }
            if (j == 10) { fa[5] = Ar[5]; fb[5] = Br[5]; }
            if (j == 14) { fa[6] = Ar[6]; fb[6] = Br[6]; }
            {   // enter pixel j+10
                const int e = j + 10;
                const float a = PXA(e), b = PXB(e);
                const float p = a + b, m = a - b;
                sa += a; sb += b; sp += p * p; sm += m * m;
            }
            Hrow[j] = make_float4(sa, sb, sp, sm);
            {   // exit pixel j
                const float a = PXA(j), b = PXB(j);
                const float p = a + b, m = a - b;
                sa -= a; sb -= b; sp -= p * p; sm -= m * m;
            }
        }
    }
    __syncthreads();

    // ---- Phase 2: vertical sliding 11-sums + SSIM. 192 threads:
    //      col = tid & 31, group = tid >> 5 (0..5), rows group*7 .. group*7+6. ----
    const float C1 = 1e-4f;
    const float C2 = 9e-4f;
    const float inv121 = 1.0f / 121.0f;
    const float inv242 = 1.0f / 242.0f;
    const float inv484 = 1.0f / 484.0f;

    float acc = 0.0f;
    if (tid < 192) {
        const int col = tid & 31;
        const int r0  = (tid >> 5) * 7;
        const bool oxok = (ox0 + col) < OUTD;

        float sa = 0.f, sb = 0.f, sp = 0.f, sm = 0.f;
        #pragma unroll
        for (int k = 0; k < 10; k++) {
            const float4 h = H[r0 + k][col];
            sa += h.x; sb += h.y; sp += h.z; sm += h.w;
        }
        #pragma unroll
        for (int j = 0; j < 7; j++) {
            {
                const float4 h = H[r0 + j + 10][col];
                sa += h.x; sb += h.y; sp += h.z; sm += h.w;
            }
            const int oy = oy0 + r0 + j;
            if (oxok && oy < OUTD) {
                const float mu1  = sa * inv121;
                const float mu2  = sb * inv121;
                const float musq = mu1 * mu1 + mu2 * mu2;
                const float mu12 = mu1 * mu2;
                const float e_sq = (sp + sm) * inv242;   // E[a^2 + b^2]
                const float e_ab = (sp - sm) * inv484;   // E[ab]
                const float vsum = e_sq - musq;          // v1 + v2
                const float v12  = e_ab - mu12;
                const float num = (2.0f * mu12 + C1) * (2.0f * v12 + C2);
                const float den = (musq + C1) * (vsum + C2);
                acc += __fdividef(num, den);
            }
            {
                const float4 h = H[r0 + j][col];
                sa -= h.x; sb -= h.y; sp -= h.z; sm -= h.w;
            }
        }
    }

    // ---- Block reduction ----
    #pragma unroll
    for (int o = 16; o > 0; o >>= 1)
        acc += __shfl_down_sync(0xffffffffu, acc, o);
    if ((tid & 31) == 0) wsum[tid >> 5] = acc;
    __syncthreads();
    if (tid == 0) {
        float t = 0.0f;
        #pragma unroll
        for (int i = 0; i < 8; i++) t += wsum[i];
        const float scale = 1.0f / (3.0f * (float)OUTD * (float)OUTD);
        atomicAdd(out + batch, t * scale);
    }
}

extern "C" void kernel_launch(void* const* d_in, const int* in_sizes, int n_in,
                              void* d_out, int out_size) {
    const float* img1 = (const float*)d_in[0];
    const float* img2 = (const float*)d_in[1];
    float* out = (float*)d_out;

    cudaFuncSetAttribute(ssim_kernel,
                         cudaFuncAttributeMaxDynamicSharedMemorySize, SMEM_TOTAL);

    ssim_zero_kernel<<<1, 32>>>(out, out_size);

    dim3 block(256);
    dim3 grid((OUTD + TILE_W - 1) / TILE_W,   // 16
              (OUTD + TILE_H - 1) / TILE_H,   // 12
              NPLANE);                        // 48
    ssim_kernel<<<grid, block, SMEM_TOTAL>>>(img1, img2, out);
}

// round 11
// speedup vs baseline: 1.1228x; 1.1228x over previous
#include <cuda_runtime.h>

#define TILE_W  54          // output cols per block
#define TILE_H  32          // output rows per block
#define VCOLS   64          // input cols = TILE_W + 10
#define VSTR    65          // V row stride in float4 (odd -> conflict-free col access)
#define IMG     512
#define OUTD    502
#define NPLANE  48

#define V_BYTES    (TILE_H * VSTR * 16)     // 33280
#define SMEM_TOTAL (V_BYTES + 64)           // 33344 -> 6 CTAs/SM (reg-capped)

__global__ void ssim_zero_kernel(float* out, int n) {
    int i = threadIdx.x;
    if (i < n) out[i] = 0.0f;
}

__global__ __launch_bounds__(256, 6) void ssim_kernel(const float* __restrict__ img1,
                                                      const float* __restrict__ img2,
                                                      float* __restrict__ out) {
    extern __shared__ char smem_raw[];
    float4 (*V)[VSTR] = (float4 (*)[VSTR])smem_raw;   // vertical 11-sums, 32 rows x 64 cols
    float* wsum = (float*)(smem_raw + V_BYTES);

    const int plane = blockIdx.z;
    const int batch = plane / 3;
    const int ox0 = blockIdx.x * TILE_W;
    const int oy0 = blockIdx.y * TILE_H;

    const float* __restrict__ p1 = img1 + (size_t)plane * IMG * IMG;
    const float* __restrict__ p2 = img2 + (size_t)plane * IMG * IMG;

    const int tid = threadIdx.x;

    // ---- Phase 1: vertical sliding 11-sums straight from GMEM (coalesced).
    //      256 threads: col c = tid&63, chunk = tid>>6 -> V rows chunk*8..chunk*8+7.
    //      Enter+exit loads; exits are L1 hits (each line touched twice).
    //      Out-of-image coords clamped (only feed guarded outputs). ----
    {
        const int c     = tid & 63;
        const int chunk = tid >> 6;
        const int r0    = chunk * 8;
        const int gx    = min(ox0 + c, IMG - 1);
        const float* __restrict__ q1 = p1 + gx;
        const float* __restrict__ q2 = p2 + gx;

        float sa = 0.f, sb = 0.f, sp = 0.f, sm = 0.f;
        #pragma unroll
        for (int k = 0; k < 10; k++) {
            const int gy = min(oy0 + r0 + k, IMG - 1);
            const float a = __saturatef(__ldg(q1 + gy * IMG));
            const float b = __saturatef(__ldg(q2 + gy * IMG));
            const float pq = a + b, mq = a - b;
            sa += a; sb += b; sp += pq * pq; sm += mq * mq;
        }
        #pragma unroll
        for (int j = 0; j < 8; j++) {
            {   // enter input row r0+j+10
                const int gy = min(oy0 + r0 + j + 10, IMG - 1);
                const float a = __saturatef(__ldg(q1 + gy * IMG));
                const float b = __saturatef(__ldg(q2 + gy * IMG));
                const float pq = a + b, mq = a - b;
                sa += a; sb += b; sp += pq * pq; sm += mq * mq;
            }
            V[r0 + j][c] = make_float4(sa, sb, sp, sm);
            {   // exit input row r0+j (L1-resident re-load)
                const int gy = min(oy0 + r0 + j, IMG - 1);
                const float a = __saturatef(__ldg(q1 + gy * IMG));
                const float b = __saturatef(__ldg(q2 + gy * IMG));
                const float pq = a + b, mq = a - b;
                sa -= a; sb -= b; sp -= pq * pq; sm -= mq * mq;
            }
        }
    }
    __syncthreads();

    // ---- Phase 2: horizontal sliding 11-sums of V + SSIM.
    //      256 threads: row = tid&31, span = tid>>5 (8 spans of 7 outputs). ----
    const float C1 = 1e-4f;
    const float C2 = 9e-4f;
    const float inv121 = 1.0f / 121.0f;
    const float inv242 = 1.0f / 242.0f;
    const float inv484 = 1.0f / 484.0f;

    float acc = 0.0f;
    {
        const int row = tid & 31;
        const int s0  = (tid >> 5) * 7;
        const bool rowok = (oy0 + row) < OUTD;

        float sa = 0.f, sb = 0.f, sp = 0.f, sm = 0.f;
        #pragma unroll
        for (int k = 0; k < 10; k++) {
            const float4 h = V[row][s0 + k];
            sa += h.x; sb += h.y; sp += h.z; sm += h.w;
        }
        #pragma unroll
        for (int j = 0; j < 7; j++) {
            if (s0 + j < TILE_W) {          // last span covers only 5 outputs
                {
                    const float4 h = V[row][s0 + j + 10];
                    sa += h.x; sb += h.y; sp += h.z; sm += h.w;
                }
                const int ox = ox0 + s0 + j;
                if (rowok && ox < OUTD) {
                    const float mu1  = sa * inv121;
                    const float mu2  = sb * inv121;
                    const float musq = mu1 * mu1 + mu2 * mu2;
                    const float mu12 = mu1 * mu2;
                    const float e_sq = (sp + sm) * inv242;   // E[a^2 + b^2]
                    const float e_ab = (sp - sm) * inv484;   // E[ab]
                    const float vsum = e_sq - musq;          // v1 + v2
                    const float v12  = e_ab - mu12;
                    const float num = (2.0f * mu12 + C1) * (2.0f * v12 + C2);
                    const float den = (musq + C1) * (vsum + C2);
                    acc += __fdividef(num, den);
                }
                {
                    const float4 h = V[row][s0 + j];
                    sa -= h.x; sb -= h.y; sp -= h.z; sm -= h.w;
                }
            }
        }
    }

    // ---- Block reduction ----
    #pragma unroll
    for (int o = 16; o > 0; o >>= 1)
        acc += __shfl_down_sync(0xffffffffu, acc, o);
    if ((tid & 31) == 0) wsum[tid >> 5] = acc;
    __syncthreads();
    if (tid == 0) {
        float t = 0.0f;
        #pragma unroll
        for (int i = 0; i < 8; i++) t += wsum[i];
        const float scale = 1.0f / (3.0f * (float)OUTD * (float)OUTD);
        atomicAdd(out + batch, t * scale);
    }
}

extern "C" void kernel_launch(void* const* d_in, const int* in_sizes, int n_in,
                              void* d_out, int out_size) {
    const float* img1 = (const float*)d_in[0];
    const float* img2 = (const float*)d_in[1];
    float* out = (float*)d_out;

    cudaFuncSetAttribute(ssim_kernel,
                         cudaFuncAttributeMaxDynamicSharedMemorySize, SMEM_TOTAL);

    ssim_zero_kernel<<<1, 32>>>(out, out_size);

    dim3 block(256);
    dim3 grid((OUTD + TILE_W - 1) / TILE_W,   // 10
              (OUTD + TILE_H - 1) / TILE_H,   // 16
              NPLANE);                        // 48
    ssim_kernel<<<grid, block, SMEM_TOTAL>>>(img1, img2, out);
}

// round 12
// speedup vs baseline: 1.2308x; 1.0962x over previous
#include <cuda_runtime.h>

#define TILE_W  54          // output cols per block
#define TILE_H  32          // output rows per block
#define VCOLS   64          // input cols = TILE_W + 10
#define VSTR    65          // V row stride in float4 (odd -> conflict-free col access)
#define IMG     512
#define OUTD    502
#define NPLANE  48

#define V_BYTES    (TILE_H * VSTR * 16)     // 33280
#define SMEM_TOTAL (V_BYTES + 64)           // 33344 -> 6 CTAs/SM

__global__ void ssim_zero_kernel(float* out, int n) {
    int i = threadIdx.x;
    if (i < n) out[i] = 0.0f;
}

__global__ __launch_bounds__(256, 6) void ssim_kernel(const float* __restrict__ img1,
                                                      const float* __restrict__ img2,
                                                      float* __restrict__ out) {
    extern __shared__ char smem_raw[];
    float4 (*V)[VSTR] = (float4 (*)[VSTR])smem_raw;   // vertical 11-sums, 32 rows x 64 cols
    float* wsum = (float*)(smem_raw + V_BYTES);

    const int plane = blockIdx.z;
    const int batch = plane / 3;
    const int ox0 = blockIdx.x * TILE_W;
    const int oy0 = blockIdx.y * TILE_H;

    const float* __restrict__ p1 = img1 + (size_t)plane * IMG * IMG;
    const float* __restrict__ p2 = img2 + (size_t)plane * IMG * IMG;

    const int tid = threadIdx.x;

    // ---- Phase 1: vertical sliding 11-sums straight from GMEM (coalesced).
    //      256 threads: col c = tid&63, chunk = tid>>6 -> V rows chunk*8..chunk*8+7. ----
    {
        const int c     = tid & 63;
        const int r0    = (tid >> 6) * 8;

        // Block-uniform fast path: whole 42-row x 64-col input window in-bounds.
        if (oy0 + TILE_H + 10 <= IMG && ox0 + VCOLS <= IMG) {
            // All row addresses are base + k*IMG with compile-time k -> LDG [R, imm].
            const float* __restrict__ q1 = p1 + (size_t)(oy0 + r0) * IMG + (ox0 + c);
            const float* __restrict__ q2 = p2 + (size_t)(oy0 + r0) * IMG + (ox0 + c);

            float sa = 0.f, sb = 0.f, sp = 0.f, sm = 0.f;
            #pragma unroll
            for (int k = 0; k < 10; k++) {
                const float a = __saturatef(__ldg(q1 + k * IMG));
                const float b = __saturatef(__ldg(q2 + k * IMG));
                const float pq = a + b, mq = a - b;
                sa += a; sb += b; sp += pq * pq; sm += mq * mq;
            }
            #pragma unroll
            for (int j = 0; j < 8; j++) {
                {   // enter row j+10
                    const float a = __saturatef(__ldg(q1 + (j + 10) * IMG));
                    const float b = __saturatef(__ldg(q2 + (j + 10) * IMG));
                    const float pq = a + b, mq = a - b;
                    sa += a; sb += b; sp += pq * pq; sm += mq * mq;
                }
                V[r0 + j][c] = make_float4(sa, sb, sp, sm);
                {   // exit row j (identical address to prologue load -> CSE/L1 hit)
                    const float a = __saturatef(__ldg(q1 + j * IMG));
                    const float b = __saturatef(__ldg(q2 + j * IMG));
                    const float pq = a + b, mq = a - b;
                    sa -= a; sb -= b; sp -= pq * pq; sm -= mq * mq;
                }
            }
        } else {
            // Boundary tiles: clamped coordinates (clamped lanes/rows only feed
            // guarded-out outputs).
            const int gx = min(ox0 + c, IMG - 1);
            const float* __restrict__ q1 = p1 + gx;
            const float* __restrict__ q2 = p2 + gx;

            float sa = 0.f, sb = 0.f, sp = 0.f, sm = 0.f;
            #pragma unroll
            for (int k = 0; k < 10; k++) {
                const int gy = min(oy0 + r0 + k, IMG - 1);
                const float a = __saturatef(__ldg(q1 + gy * IMG));
                const float b = __saturatef(__ldg(q2 + gy * IMG));
                const float pq = a + b, mq = a - b;
                sa += a; sb += b; sp += pq * pq; sm += mq * mq;
            }
            #pragma unroll
            for (int j = 0; j < 8; j++) {
                {
                    const int gy = min(oy0 + r0 + j + 10, IMG - 1);
                    const float a = __saturatef(__ldg(q1 + gy * IMG));
                    const float b = __saturatef(__ldg(q2 + gy * IMG));
                    const float pq = a + b, mq = a - b;
                    sa += a; sb += b; sp += pq * pq; sm += mq * mq;
                }
                V[r0 + j][c] = make_float4(sa, sb, sp, sm);
                {
                    const int gy = min(oy0 + r0 + j, IMG - 1);
                    const float a = __saturatef(__ldg(q1 + gy * IMG));
                    const float b = __saturatef(__ldg(q2 + gy * IMG));
                    const float pq = a + b, mq = a - b;
                    sa -= a; sb -= b; sp -= pq * pq; sm -= mq * mq;
                }
            }
        }
    }
    __syncthreads();

    // ---- Phase 2: horizontal sliding 11-sums of V + SSIM.
    //      256 threads: row = tid&31, span = tid>>5 (8 spans of 7 outputs). ----
    const float C1 = 1e-4f;
    const float C2 = 9e-4f;
    const float inv121 = 1.0f / 121.0f;
    const float inv242 = 1.0f / 242.0f;
    const float inv484 = 1.0f / 484.0f;

    float acc = 0.0f;
    {
        const int row = tid & 31;
        const int s0  = (tid >> 5) * 7;
        const bool rowok = (oy0 + row) < OUTD;

        float sa = 0.f, sb = 0.f, sp = 0.f, sm = 0.f;
        #pragma unroll
        for (int k = 0; k < 10; k++) {
            const float4 h = V[row][s0 + k];
            sa += h.x; sb += h.y; sp += h.z; sm += h.w;
        }
        #pragma unroll
        for (int j = 0; j < 7; j++) {
            if (s0 + j < TILE_W) {          // last span covers only 5 outputs
                {
                    const float4 h = V[row][s0 + j + 10];
                    sa += h.x; sb += h.y; sp += h.z; sm += h.w;
                }
                const int ox = ox0 + s0 + j;
                if (rowok && ox < OUTD) {
                    const float mu1  = sa * inv121;
                    const float mu2  = sb * inv121;
                    const float musq = mu1 * mu1 + mu2 * mu2;
                    const float mu12 = mu1 * mu2;
                    const float e_sq = (sp + sm) * inv242;   // E[a^2 + b^2]
                    const float e_ab = (sp - sm) * inv484;   // E[ab]
                    const float vsum = e_sq - musq;          // v1 + v2
                    const float v12  = e_ab - mu12;
                    const float num = (2.0f * mu12 + C1) * (2.0f * v12 + C2);
                    const float den = (musq + C1) * (vsum + C2);
                    acc += __fdividef(num, den);
                }
                {
                    const float4 h = V[row][s0 + j];
                    sa -= h.x; sb -= h.y; sp -= h.z; sm -= h.w;
                }
            }
        }
    }

    // ---- Block reduction ----
    #pragma unroll
    for (int o = 16; o > 0; o >>= 1)
        acc += __shfl_down_sync(0xffffffffu, acc, o);
    if ((tid & 31) == 0) wsum[tid >> 5] = acc;
    __syncthreads();
    if (tid == 0) {
        float t = 0.0f;
        #pragma unroll
        for (int i = 0; i < 8; i++) t += wsum[i];
        const float scale = 1.0f / (3.0f * (float)OUTD * (float)OUTD);
        atomicAdd(out + batch, t * scale);
    }
}

extern "C" void kernel_launch(void* const* d_in, const int* in_sizes, int n_in,
                              void* d_out, int out_size) {
    const float* img1 = (const float*)d_in[0];
    const float* img2 = (const float*)d_in[1];
    float* out = (float*)d_out;

    cudaFuncSetAttribute(ssim_kernel,
                         cudaFuncAttributeMaxDynamicSharedMemorySize, SMEM_TOTAL);

    ssim_zero_kernel<<<1, 32>>>(out, out_size);

    dim3 block(256);
    dim3 grid((OUTD + TILE_W - 1) / TILE_W,   // 10
              (OUTD + TILE_H - 1) / TILE_H,   // 16
              NPLANE);                        // 48
    ssim_kernel<<<grid, block, SMEM_TOTAL>>>(img1, img2, out);
}